// round 14
// baseline (speedup 1.0000x reference)
#include <cuda_runtime.h>
#include <math.h>
#include <stdint.h>

// Lin2d: x <- x @ Mt, 1000 times, Mt = [[c,-s],[s,c]] (float32 c,s).
// Collapsed to one complex multiply by w = (c - i*s)^1000 (host double math).
// Streaming kernel using sm_103a 256-bit global loads (LDG.E.256): each
// thread loads 8 floats (4 states) in ONE instruction, rotates, stores as
// two 128-bit streaming stores. Flat contiguous tiling (best layout found).

__global__ void __launch_bounds__(256)
lin2d_apply_kernel(const float* __restrict__ in,
                   float* __restrict__ out,
                   int n8, float wr, float wi) {
    int i = blockIdx.x * blockDim.x + threadIdx.x;
    if (i >= n8) return;

    const float* p = in + (size_t)i * 8;
    float*       q = out + (size_t)i * 8;

    unsigned a0, a1, a2, a3, a4, a5, a6, a7;
    asm("ld.global.nc.v8.b32 {%0,%1,%2,%3,%4,%5,%6,%7}, [%8];"
        : "=r"(a0), "=r"(a1), "=r"(a2), "=r"(a3),
          "=r"(a4), "=r"(a5), "=r"(a6), "=r"(a7)
        : "l"(p));

    float x0 = __uint_as_float(a0), y0 = __uint_as_float(a1);
    float x1 = __uint_as_float(a2), y1 = __uint_as_float(a3);
    float x2 = __uint_as_float(a4), y2 = __uint_as_float(a5);
    float x3 = __uint_as_float(a6), y3 = __uint_as_float(a7);

    float4 r0, r1;
    r0.x = fmaf(wr, x0, -wi * y0);
    r0.y = fmaf(wi, x0,  wr * y0);
    r0.z = fmaf(wr, x1, -wi * y1);
    r0.w = fmaf(wi, x1,  wr * y1);
    r1.x = fmaf(wr, x2, -wi * y2);
    r1.y = fmaf(wi, x2,  wr * y2);
    r1.z = fmaf(wr, x3, -wi * y3);
    r1.w = fmaf(wi, x3,  wr * y3);

    __stcs((float4*)q,     r0);
    __stcs((float4*)q + 1, r1);
}

extern "C" void kernel_launch(void* const* d_in, const int* in_sizes, int n_in,
                              void* d_out, int out_size) {
    const float* x = (const float*)d_in[0];
    float* y = (float*)d_out;
    const int n = in_sizes[0];       // total floats = BATCH*2 = 33,554,432
    const int n8 = n / 8;            // 8 floats per thread (n divisible by 8)

    // Host-side constants (pure math at capture time; deterministic).
    const double theta = 3.14159265358979323846 / 100.0;
    const double c = (double)((float)cos(theta));
    const double s = (double)((float)sin(theta));
    const int N = 1000;
    const double r   = hypot(c, s);
    const double phi = atan2(s, c);
    const double mag = pow(r, (double)N);
    // w = (c - i*s)^N = mag * (cos(N*phi) - i*sin(N*phi))
    const float wr = (float)(mag * cos((double)N * phi));
    const float wi = (float)(-mag * sin((double)N * phi));

    const int threads = 256;
    const int blocks = (n8 + threads - 1) / threads;
    lin2d_apply_kernel<<<blocks, threads>>>(x, y, n8, wr, wi);
}